// round 5
// baseline (speedup 1.0000x reference)
#include <cuda_runtime.h>
#include <cstdint>

// Problem constants
#define NN   131072      // total nodes (B*N)
#define DIMF 128         // embedding dim
#define EDG  1048576     // edges
#define INF  74          // input feats

// ---------------- device scratch (allocation-free rule) ----------------
__device__ float g_hA[NN * DIMF];     // 64MB ping
__device__ float g_hB[NN * DIMF];     // 64MB pong
__device__ float g_nsrc[NN];          // rsqrt(max(deg_out,1))
__device__ float g_ndst[NN];          // rsqrt(max(deg_in,1))
__device__ int   g_deg_out[NN];
__device__ int   g_deg_in[NN];
__device__ int   g_cursor[NN];
__device__ int   g_rstart[NN];        // CSR row starts (by dst)
__device__ int   g_csr[EDG];          // src index per CSR slot
__device__ int   g_bsum[128];
__device__ int   g_boff[128];

#define KP_I 80          // init K padded 74 -> 80
// pre-transposed tf32 weights: WT[n][k] = tf32(W[k][n])
__device__ float g_WT1[128 * 128];
__device__ float g_WT2[128 * 128];
__device__ float g_WT3[128 * 128];
__device__ float g_WTi[128 * KP_I];

// ---------------- tf32 helpers ----------------
__device__ __forceinline__ float to_tf32(float x) {
    uint32_t u;
    asm("cvt.rna.tf32.f32 %0, %1;" : "=r"(u) : "f"(x));
    return __uint_as_float(u);
}

// D += A*B, m16n8k8 tf32 (A row-major frag, B col-major frag from Bs[n][k])
__device__ __forceinline__ void mma_tf32(float d[4],
                                         uint32_t a0, uint32_t a1, uint32_t a2, uint32_t a3,
                                         uint32_t b0, uint32_t b1) {
    asm volatile(
        "mma.sync.aligned.m16n8k8.row.col.f32.tf32.tf32.f32 "
        "{%0,%1,%2,%3}, {%4,%5,%6,%7}, {%8,%9}, {%0,%1,%2,%3};"
        : "+f"(d[0]), "+f"(d[1]), "+f"(d[2]), "+f"(d[3])
        : "r"(a0), "r"(a1), "r"(a2), "r"(a3), "r"(b0), "r"(b1));
}

// ---------------- preprocessing ----------------
__global__ void k_zero() {
    int i = blockIdx.x * blockDim.x + threadIdx.x;
    if (i < NN) { g_deg_out[i] = 0; g_deg_in[i] = 0; g_cursor[i] = 0; }
}

__global__ void k_count(const int* __restrict__ src, const int* __restrict__ dst) {
    int stride = gridDim.x * blockDim.x;
    for (int e = blockIdx.x * blockDim.x + threadIdx.x; e < EDG; e += stride) {
        atomicAdd(&g_deg_out[src[e]], 1);
        atomicAdd(&g_deg_in[dst[e]], 1);
    }
}

__global__ void k_scanA() {
    __shared__ int sh[1024];
    int i = blockIdx.x * 1024 + threadIdx.x;
    int v = g_deg_in[i];
    sh[threadIdx.x] = v;
    __syncthreads();
#pragma unroll
    for (int off = 1; off < 1024; off <<= 1) {
        int t = (threadIdx.x >= off) ? sh[threadIdx.x - off] : 0;
        __syncthreads();
        sh[threadIdx.x] += t;
        __syncthreads();
    }
    g_rstart[i] = sh[threadIdx.x] - v;
    if (threadIdx.x == 1023) g_bsum[blockIdx.x] = sh[1023];
}

__global__ void k_scanB() {
    __shared__ int sh[128];
    int v = g_bsum[threadIdx.x];
    sh[threadIdx.x] = v;
    __syncthreads();
#pragma unroll
    for (int off = 1; off < 128; off <<= 1) {
        int t = (threadIdx.x >= off) ? sh[threadIdx.x - off] : 0;
        __syncthreads();
        sh[threadIdx.x] += t;
        __syncthreads();
    }
    g_boff[threadIdx.x] = sh[threadIdx.x] - v;
}

__global__ void k_scanC_norm() {
    int i = blockIdx.x * blockDim.x + threadIdx.x;
    if (i < NN) {
        g_rstart[i] += g_boff[i >> 10];
        g_nsrc[i] = rsqrtf((float)max(g_deg_out[i], 1));
        g_ndst[i] = rsqrtf((float)max(g_deg_in[i], 1));
    }
}

__global__ void k_fill(const int* __restrict__ src, const int* __restrict__ dst) {
    int stride = gridDim.x * blockDim.x;
    for (int e = blockIdx.x * blockDim.x + threadIdx.x; e < EDG; e += stride) {
        int d = dst[e];
        int pos = atomicAdd(&g_cursor[d], 1);
        g_csr[g_rstart[d] + pos] = src[e];
    }
}

// Transpose (+tf32-round) all weights once.
__global__ void k_wt(const float* __restrict__ Wi, const float* __restrict__ W1,
                     const float* __restrict__ W2, const float* __restrict__ W3) {
    int i = blockIdx.x * blockDim.x + threadIdx.x;
    if (i < 128 * 128) {
        int n = i >> 7, k = i & 127;
        g_WT1[i] = to_tf32(W1[k * 128 + n]);
        g_WT2[i] = to_tf32(W2[k * 128 + n]);
        g_WT3[i] = to_tf32(W3[k * 128 + n]);
    }
    if (i < 128 * KP_I) {
        int n = i / KP_I, k = i - n * KP_I;
        g_WTi[i] = (k < INF) ? to_tf32(Wi[k * 128 + n]) : 0.f;
    }
}

// ---------------- shared tile strides (floats) ----------------
#define LDA 132          // 128 k + 4 pad: conflict-free frags, 16B-aligned rows
#define LDI 84           // 80 k + 4 pad

// ================= fused layer kernel =================
// BM=64 rows/block, 256 threads (8 warps), 2 CTAs/SM for cross-CTA phase overlap.
// Phase 1: CSR gather + ndst scale -> As (tf32).  Stage WT -> Bs (float4 copy).
// Phase 2: warp-tiled m16n8k8 tf32 mma, 32x32 per warp (2x4 warp grid).
// MODE 1: out scaled by nsrc (feeds next gather). MODE 2: plain output.
template <int MODE>
__global__ void __launch_bounds__(256, 2)
k_layer_mma(const float* __restrict__ hn,
            const float* __restrict__ Wt,
            const float* __restrict__ bias,
            float* __restrict__ out) {
    extern __shared__ float sm[];
    float* As = sm;                    // [64][LDA]
    float* Bs = sm + 64 * LDA;         // [128][LDA]  Bs[n][k] = tf32(W[k][n])
    const int tid = threadIdx.x;
    const int lane = tid & 31, warp = tid >> 5;
    const int rowBase = blockIdx.x * 64;

    // ---- stage B from pre-transposed WT (float4) ----
    {
        const float4* Wt4 = (const float4*)Wt;
        for (int idx = tid; idx < 128 * 32; idx += 256) {
            int n = idx >> 5, kq = idx & 31;
            *(float4*)&Bs[n * LDA + kq * 4] = Wt4[idx];
        }
    }

    // ---- gather + ndst scale -> A tile (tf32), 8 rows per warp, MLP-8 ----
    const float4* h4 = (const float4*)hn;
#pragma unroll
    for (int rr = 0; rr < 8; ++rr) {
        int r = warp * 8 + rr;
        int n = rowBase + r;
        int j0 = g_rstart[n];
        int cnt = g_deg_in[n];
        float4 acc = make_float4(0.f, 0.f, 0.f, 0.f);
        int j = 0;
        for (; j + 8 <= cnt; j += 8) {
            int s0 = g_csr[j0 + j];
            int s1 = g_csr[j0 + j + 1];
            int s2 = g_csr[j0 + j + 2];
            int s3 = g_csr[j0 + j + 3];
            int s4 = g_csr[j0 + j + 4];
            int s5 = g_csr[j0 + j + 5];
            int s6 = g_csr[j0 + j + 6];
            int s7 = g_csr[j0 + j + 7];
            float4 v0 = h4[s0 * 32 + lane];
            float4 v1 = h4[s1 * 32 + lane];
            float4 v2 = h4[s2 * 32 + lane];
            float4 v3 = h4[s3 * 32 + lane];
            float4 v4 = h4[s4 * 32 + lane];
            float4 v5 = h4[s5 * 32 + lane];
            float4 v6 = h4[s6 * 32 + lane];
            float4 v7 = h4[s7 * 32 + lane];
            acc.x += ((v0.x + v1.x) + (v2.x + v3.x)) + ((v4.x + v5.x) + (v6.x + v7.x));
            acc.y += ((v0.y + v1.y) + (v2.y + v3.y)) + ((v4.y + v5.y) + (v6.y + v7.y));
            acc.z += ((v0.z + v1.z) + (v2.z + v3.z)) + ((v4.z + v5.z) + (v6.z + v7.z));
            acc.w += ((v0.w + v1.w) + (v2.w + v3.w)) + ((v4.w + v5.w) + (v6.w + v7.w));
        }
        for (; j + 2 <= cnt; j += 2) {
            int s0 = g_csr[j0 + j];
            int s1 = g_csr[j0 + j + 1];
            float4 v0 = h4[s0 * 32 + lane];
            float4 v1 = h4[s1 * 32 + lane];
            acc.x += v0.x + v1.x; acc.y += v0.y + v1.y;
            acc.z += v0.z + v1.z; acc.w += v0.w + v1.w;
        }
        for (; j < cnt; ++j) {
            int s = g_csr[j0 + j];
            float4 v = h4[s * 32 + lane];
            acc.x += v.x; acc.y += v.y; acc.z += v.z; acc.w += v.w;
        }
        float nd = g_ndst[n];
        float4 st;
        st.x = to_tf32(acc.x * nd);
        st.y = to_tf32(acc.y * nd);
        st.z = to_tf32(acc.z * nd);
        st.w = to_tf32(acc.w * nd);
        *(float4*)&As[r * LDA + lane * 4] = st;
    }
    __syncthreads();

    // ---- Phase 2: warp 32x32 tile; warp grid 2x4 ----
    const int wr = warp >> 2, wc = warp & 3;
    const int m0 = wr * 32, n0 = wc * 32;
    const int g = lane >> 2, tig = lane & 3;

    float D[2][4][4];
#pragma unroll
    for (int i = 0; i < 2; i++)
#pragma unroll
        for (int j = 0; j < 4; j++)
#pragma unroll
            for (int q = 0; q < 4; q++) D[i][j][q] = 0.f;

    const uint32_t* Au = (const uint32_t*)As;
    const uint32_t* Bu = (const uint32_t*)Bs;

#pragma unroll 4
    for (int k0 = 0; k0 < 128; k0 += 8) {
        uint32_t a[2][4];
#pragma unroll
        for (int i = 0; i < 2; i++) {
            int mr = m0 + i * 16 + g;
            a[i][0] = Au[mr * LDA + k0 + tig];
            a[i][1] = Au[(mr + 8) * LDA + k0 + tig];
            a[i][2] = Au[mr * LDA + k0 + tig + 4];
            a[i][3] = Au[(mr + 8) * LDA + k0 + tig + 4];
        }
        uint32_t b[4][2];
#pragma unroll
        for (int j = 0; j < 4; j++) {
            int nc = n0 + j * 8 + g;
            b[j][0] = Bu[nc * LDA + k0 + tig];
            b[j][1] = Bu[nc * LDA + k0 + tig + 4];
        }
#pragma unroll
        for (int i = 0; i < 2; i++)
#pragma unroll
            for (int j = 0; j < 4; j++)
                mma_tf32(D[i][j], a[i][0], a[i][1], a[i][2], a[i][3], b[j][0], b[j][1]);
    }

    // ---- Epilogue ----
#pragma unroll
    for (int i = 0; i < 2; i++) {
        int r0 = rowBase + m0 + i * 16 + g;     // rows r0 and r0+8
        float ns0 = (MODE == 1) ? g_nsrc[r0] : 1.f;
        float ns1 = (MODE == 1) ? g_nsrc[r0 + 8] : 1.f;
#pragma unroll
        for (int j = 0; j < 4; j++) {
            int col = n0 + j * 8 + tig * 2;
            float bx = bias[col], by = bias[col + 1];
            float2 v0, v1;
            v0.x = fmaxf(D[i][j][0] + bx, 0.f) * ns0;
            v0.y = fmaxf(D[i][j][1] + by, 0.f) * ns0;
            v1.x = fmaxf(D[i][j][2] + bx, 0.f) * ns1;
            v1.y = fmaxf(D[i][j][3] + by, 0.f) * ns1;
            *(float2*)&out[(size_t)r0 * 128 + col] = v0;
            *(float2*)&out[(size_t)(r0 + 8) * 128 + col] = v1;
        }
    }
}

// ================= init kernel: hA = (x @ W_init) * nsrc =================
__global__ void __launch_bounds__(256, 2)
k_init_mma(const float* __restrict__ x) {
    extern __shared__ float sm[];
    float* As = sm;                    // [64][LDI]
    float* Bs = sm + 64 * LDI;         // [128][LDI]
    const int tid = threadIdx.x;
    const int lane = tid & 31, warp = tid >> 5;
    const int rowBase = blockIdx.x * 64;

    // B from g_WTi (float4: 128 rows x 20 quads)
    {
        const float4* Wt4 = (const float4*)g_WTi;
        for (int idx = tid; idx < 128 * (KP_I / 4); idx += 256) {
            int n = idx / (KP_I / 4), kq = idx - n * (KP_I / 4);
            *(float4*)&Bs[n * LDI + kq * 4] = Wt4[idx];
        }
    }
    // A: [64 r][80 k], zero-pad k>=74 (scalar: x rows are 74-float, unaligned)
    for (int idx = tid; idx < 64 * KP_I; idx += 256) {
        int r = idx / KP_I, k = idx - r * KP_I;
        float v = (k < INF) ? to_tf32(x[(size_t)(rowBase + r) * INF + k]) : 0.f;
        As[r * LDI + k] = v;
    }
    __syncthreads();

    const int wr = warp >> 2, wc = warp & 3;
    const int m0 = wr * 32, n0 = wc * 32;
    const int g = lane >> 2, tig = lane & 3;

    float D[2][4][4];
#pragma unroll
    for (int i = 0; i < 2; i++)
#pragma unroll
        for (int j = 0; j < 4; j++)
#pragma unroll
            for (int q = 0; q < 4; q++) D[i][j][q] = 0.f;

    const uint32_t* Au = (const uint32_t*)As;
    const uint32_t* Bu = (const uint32_t*)Bs;

#pragma unroll
    for (int k0 = 0; k0 < KP_I; k0 += 8) {
        uint32_t a[2][4];
#pragma unroll
        for (int i = 0; i < 2; i++) {
            int mr = m0 + i * 16 + g;
            a[i][0] = Au[mr * LDI + k0 + tig];
            a[i][1] = Au[(mr + 8) * LDI + k0 + tig];
            a[i][2] = Au[mr * LDI + k0 + tig + 4];
            a[i][3] = Au[(mr + 8) * LDI + k0 + tig + 4];
        }
        uint32_t b[4][2];
#pragma unroll
        for (int j = 0; j < 4; j++) {
            int nc = n0 + j * 8 + g;
            b[j][0] = Bu[nc * LDI + k0 + tig];
            b[j][1] = Bu[nc * LDI + k0 + tig + 4];
        }
#pragma unroll
        for (int i = 0; i < 2; i++)
#pragma unroll
            for (int j = 0; j < 4; j++)
                mma_tf32(D[i][j], a[i][0], a[i][1], a[i][2], a[i][3], b[j][0], b[j][1]);
    }

#pragma unroll
    for (int i = 0; i < 2; i++) {
        int r0 = rowBase + m0 + i * 16 + g;
        float ns0 = g_nsrc[r0];
        float ns1 = g_nsrc[r0 + 8];
#pragma unroll
        for (int j = 0; j < 4; j++) {
            int col = n0 + j * 8 + tig * 2;
            float2 v0, v1;
            v0.x = D[i][j][0] * ns0;
            v0.y = D[i][j][1] * ns0;
            v1.x = D[i][j][2] * ns1;
            v1.y = D[i][j][3] * ns1;
            *(float2*)&g_hA[(size_t)r0 * 128 + col] = v0;
            *(float2*)&g_hA[(size_t)(r0 + 8) * 128 + col] = v1;
        }
    }
}

// ---------------- launch ----------------
extern "C" void kernel_launch(void* const* d_in, const int* in_sizes, int n_in,
                              void* d_out, int out_size) {
    (void)in_sizes; (void)n_in; (void)out_size;
    const float* x   = (const float*)d_in[0];
    const int*   src = (const int*)d_in[1];
    const int*   dst = (const int*)d_in[2];
    const float* Wi  = (const float*)d_in[3];
    const float* W1  = (const float*)d_in[4];
    const float* b1  = (const float*)d_in[5];
    const float* W2  = (const float*)d_in[6];
    const float* b2  = (const float*)d_in[7];
    const float* W3  = (const float*)d_in[8];
    const float* b3  = (const float*)d_in[9];
    float* out = (float*)d_out;

    const int SMEM_LAYER = (64 * LDA + 128 * LDA) * 4;   // 101,376 B (2 CTAs/SM)
    const int SMEM_INIT  = (64 * LDI + 128 * LDI) * 4;   //  64,512 B

    cudaFuncSetAttribute(k_init_mma, cudaFuncAttributeMaxDynamicSharedMemorySize, SMEM_INIT);
    cudaFuncSetAttribute(k_layer_mma<1>, cudaFuncAttributeMaxDynamicSharedMemorySize, SMEM_LAYER);
    cudaFuncSetAttribute(k_layer_mma<2>, cudaFuncAttributeMaxDynamicSharedMemorySize, SMEM_LAYER);

    float *hA, *hB, *wt1, *wt2, *wt3;
    cudaGetSymbolAddress((void**)&hA, g_hA);
    cudaGetSymbolAddress((void**)&hB, g_hB);
    cudaGetSymbolAddress((void**)&wt1, g_WT1);
    cudaGetSymbolAddress((void**)&wt2, g_WT2);
    cudaGetSymbolAddress((void**)&wt3, g_WT3);

    // graph preprocessing
    k_zero<<<(NN + 255) / 256, 256>>>();
    k_count<<<1024, 256>>>(src, dst);
    k_scanA<<<NN / 1024, 1024>>>();
    k_scanB<<<1, 128>>>();
    k_scanC_norm<<<(NN + 255) / 256, 256>>>();
    k_fill<<<1024, 256>>>(src, dst);
    k_wt<<<64, 256>>>(Wi, W1, W2, W3);

    // hA = (x @ W_init) * nrm_src
    k_init_mma<<<NN / 64, 256, SMEM_INIT>>>(x);

    // 3 GCN layers (ping-pong; layer 3 writes d_out unscaled)
    k_layer_mma<1><<<NN / 64, 256, SMEM_LAYER>>>(hA, wt1, b1, hB);
    k_layer_mma<1><<<NN / 64, 256, SMEM_LAYER>>>(hB, wt2, b2, hA);
    k_layer_mma<2><<<NN / 64, 256, SMEM_LAYER>>>(hA, wt3, b3, out);
}

// round 6
// speedup vs baseline: 1.1551x; 1.1551x over previous
#include <cuda_runtime.h>
#include <cstdint>

// Problem constants
#define NN   131072      // total nodes (B*N)
#define DIMF 128         // embedding dim
#define EDG  1048576     // edges
#define INF  74          // input feats

// ---------------- device scratch (allocation-free rule) ----------------
__device__ float g_hA[NN * DIMF];     // 64MB ping
__device__ float g_hB[NN * DIMF];     // 64MB pong
__device__ float g_nsrc[NN];          // rsqrt(max(deg_out,1))
__device__ float g_ndst[NN];          // rsqrt(max(deg_in,1))
__device__ int   g_deg_out[NN];
__device__ int   g_deg_in[NN];
__device__ int   g_cursor[NN];
__device__ int   g_rstart[NN];        // CSR row starts (by dst)
__device__ int   g_csr[EDG];          // src index per CSR slot
__device__ int   g_bsum[128];
__device__ int   g_boff[128];

#define KP_I 80          // init K padded 74 -> 80
// pre-transposed tf32 weights: WT[n][k] = tf32(W[k][n])
__device__ float g_WT1[128 * 128];
__device__ float g_WT2[128 * 128];
__device__ float g_WT3[128 * 128];
__device__ float g_WTi[128 * KP_I];

// ---------------- tf32 helpers ----------------
__device__ __forceinline__ float to_tf32(float x) {
    uint32_t u;
    asm("cvt.rna.tf32.f32 %0, %1;" : "=r"(u) : "f"(x));
    return __uint_as_float(u);
}

// D += A*B, m16n8k8 tf32 (A row-major frag, B col-major frag from Bs[n][k])
__device__ __forceinline__ void mma_tf32(float d[4],
                                         uint32_t a0, uint32_t a1, uint32_t a2, uint32_t a3,
                                         uint32_t b0, uint32_t b1) {
    asm volatile(
        "mma.sync.aligned.m16n8k8.row.col.f32.tf32.tf32.f32 "
        "{%0,%1,%2,%3}, {%4,%5,%6,%7}, {%8,%9}, {%0,%1,%2,%3};"
        : "+f"(d[0]), "+f"(d[1]), "+f"(d[2]), "+f"(d[3])
        : "r"(a0), "r"(a1), "r"(a2), "r"(a3), "r"(b0), "r"(b1));
}

// ---------------- preprocessing ----------------
__global__ void k_zero() {
    int i = blockIdx.x * blockDim.x + threadIdx.x;
    if (i < NN) { g_deg_out[i] = 0; g_deg_in[i] = 0; g_cursor[i] = 0; }
}

__global__ void k_count(const int* __restrict__ src, const int* __restrict__ dst) {
    int stride = gridDim.x * blockDim.x;
    for (int e = blockIdx.x * blockDim.x + threadIdx.x; e < EDG; e += stride) {
        atomicAdd(&g_deg_out[src[e]], 1);
        atomicAdd(&g_deg_in[dst[e]], 1);
    }
}

__global__ void k_scanA() {
    __shared__ int sh[1024];
    int i = blockIdx.x * 1024 + threadIdx.x;
    int v = g_deg_in[i];
    sh[threadIdx.x] = v;
    __syncthreads();
#pragma unroll
    for (int off = 1; off < 1024; off <<= 1) {
        int t = (threadIdx.x >= off) ? sh[threadIdx.x - off] : 0;
        __syncthreads();
        sh[threadIdx.x] += t;
        __syncthreads();
    }
    g_rstart[i] = sh[threadIdx.x] - v;
    if (threadIdx.x == 1023) g_bsum[blockIdx.x] = sh[1023];
}

__global__ void k_scanB() {
    __shared__ int sh[128];
    int v = g_bsum[threadIdx.x];
    sh[threadIdx.x] = v;
    __syncthreads();
#pragma unroll
    for (int off = 1; off < 128; off <<= 1) {
        int t = (threadIdx.x >= off) ? sh[threadIdx.x - off] : 0;
        __syncthreads();
        sh[threadIdx.x] += t;
        __syncthreads();
    }
    g_boff[threadIdx.x] = sh[threadIdx.x] - v;
}

__global__ void k_scanC_norm() {
    int i = blockIdx.x * blockDim.x + threadIdx.x;
    if (i < NN) {
        g_rstart[i] += g_boff[i >> 10];
        g_nsrc[i] = rsqrtf((float)max(g_deg_out[i], 1));
        g_ndst[i] = rsqrtf((float)max(g_deg_in[i], 1));
    }
}

__global__ void k_fill(const int* __restrict__ src, const int* __restrict__ dst) {
    int stride = gridDim.x * blockDim.x;
    for (int e = blockIdx.x * blockDim.x + threadIdx.x; e < EDG; e += stride) {
        int d = dst[e];
        int pos = atomicAdd(&g_cursor[d], 1);
        g_csr[g_rstart[d] + pos] = src[e];
    }
}

// Transpose (+tf32-round) all weights once.
__global__ void k_wt(const float* __restrict__ Wi, const float* __restrict__ W1,
                     const float* __restrict__ W2, const float* __restrict__ W3) {
    int i = blockIdx.x * blockDim.x + threadIdx.x;
    if (i < 128 * 128) {
        int n = i >> 7, k = i & 127;
        g_WT1[i] = to_tf32(W1[k * 128 + n]);
        g_WT2[i] = to_tf32(W2[k * 128 + n]);
        g_WT3[i] = to_tf32(W3[k * 128 + n]);
    }
    if (i < 128 * KP_I) {
        int n = i / KP_I, k = i - n * KP_I;
        g_WTi[i] = (k < INF) ? to_tf32(Wi[k * 128 + n]) : 0.f;
    }
}

// ---------------- shared tile strides (floats) ----------------
#define LDA 132          // 128 k + 4 pad: conflict-free frags, 16B-aligned rows
#define LDI 84           // 80 k + 4 pad

// ================= fused layer kernel =================
// BM=128 rows/block, 512 threads (16 warps), 1 CTA/SM.
// Phase 1: CSR gather (predicated 8-wide groups, MLP~16) + ndst -> As (tf32);
//          stage pre-transposed WT -> Bs (float4).
// Phase 2: warp-tiled m16n8k8 tf32 mma, 32x32 per warp (4x4 warp grid).
// MODE 1: out scaled by nsrc (feeds next gather). MODE 2: plain output.
template <int MODE>
__global__ void __launch_bounds__(512, 1)
k_layer_mma(const float* __restrict__ hn,
            const float* __restrict__ Wt,
            const float* __restrict__ bias,
            float* __restrict__ out) {
    extern __shared__ float sm[];
    float* As = sm;                    // [128][LDA]
    float* Bs = sm + 128 * LDA;        // [128][LDA]  Bs[n][k] = tf32(W[k][n])
    const int tid = threadIdx.x;
    const int lane = tid & 31, warp = tid >> 5;
    const int rowBase = blockIdx.x * 128;

    // ---- stage B from pre-transposed WT (float4) ----
    {
        const float4* Wt4 = (const float4*)Wt;
        for (int idx = tid; idx < 128 * 32; idx += 512) {
            int n = idx >> 5, kq = idx & 31;
            *(float4*)&Bs[n * LDA + kq * 4] = Wt4[idx];
        }
    }

    // ---- gather + ndst scale -> A tile (tf32), 8 rows per warp ----
    // Every 8-group (incl. remainder) issues predicated loads: full MLP, no
    // serial dependent-load tail.
    const float4* h4 = (const float4*)hn;
    for (int rr = 0; rr < 8; ++rr) {
        int r = warp * 8 + rr;
        int n = rowBase + r;
        int j0 = g_rstart[n];
        int cnt = g_deg_in[n];
        float4 acc = make_float4(0.f, 0.f, 0.f, 0.f);
#pragma unroll 1
        for (int j = 0; j < cnt; j += 8) {
            float4 v[8];
#pragma unroll
            for (int t = 0; t < 8; ++t) {
                v[t] = make_float4(0.f, 0.f, 0.f, 0.f);
                if (j + t < cnt) {
                    int s = g_csr[j0 + j + t];
                    v[t] = h4[s * 32 + lane];
                }
            }
            acc.x += ((v[0].x + v[1].x) + (v[2].x + v[3].x)) + ((v[4].x + v[5].x) + (v[6].x + v[7].x));
            acc.y += ((v[0].y + v[1].y) + (v[2].y + v[3].y)) + ((v[4].y + v[5].y) + (v[6].y + v[7].y));
            acc.z += ((v[0].z + v[1].z) + (v[2].z + v[3].z)) + ((v[4].z + v[5].z) + (v[6].z + v[7].z));
            acc.w += ((v[0].w + v[1].w) + (v[2].w + v[3].w)) + ((v[4].w + v[5].w) + (v[6].w + v[7].w));
        }
        float nd = g_ndst[n];
        float4 st;
        st.x = to_tf32(acc.x * nd);
        st.y = to_tf32(acc.y * nd);
        st.z = to_tf32(acc.z * nd);
        st.w = to_tf32(acc.w * nd);
        *(float4*)&As[r * LDA + lane * 4] = st;
    }
    __syncthreads();

    // ---- Phase 2: warp 32x32 tile; warp grid 4x4 ----
    const int wr = warp >> 2, wc = warp & 3;
    const int m0 = wr * 32, n0 = wc * 32;
    const int g = lane >> 2, tig = lane & 3;

    float D[2][4][4];
#pragma unroll
    for (int i = 0; i < 2; i++)
#pragma unroll
        for (int j = 0; j < 4; j++)
#pragma unroll
            for (int q = 0; q < 4; q++) D[i][j][q] = 0.f;

    const uint32_t* Au = (const uint32_t*)As;
    const uint32_t* Bu = (const uint32_t*)Bs;

#pragma unroll 4
    for (int k0 = 0; k0 < 128; k0 += 8) {
        uint32_t a[2][4];
#pragma unroll
        for (int i = 0; i < 2; i++) {
            int mr = m0 + i * 16 + g;
            a[i][0] = Au[mr * LDA + k0 + tig];
            a[i][1] = Au[(mr + 8) * LDA + k0 + tig];
            a[i][2] = Au[mr * LDA + k0 + tig + 4];
            a[i][3] = Au[(mr + 8) * LDA + k0 + tig + 4];
        }
        uint32_t b[4][2];
#pragma unroll
        for (int j = 0; j < 4; j++) {
            int nc = n0 + j * 8 + g;
            b[j][0] = Bu[nc * LDA + k0 + tig];
            b[j][1] = Bu[nc * LDA + k0 + tig + 4];
        }
#pragma unroll
        for (int i = 0; i < 2; i++)
#pragma unroll
            for (int j = 0; j < 4; j++)
                mma_tf32(D[i][j], a[i][0], a[i][1], a[i][2], a[i][3], b[j][0], b[j][1]);
    }

    // ---- Epilogue ----
#pragma unroll
    for (int i = 0; i < 2; i++) {
        int r0 = rowBase + m0 + i * 16 + g;     // rows r0 and r0+8
        float ns0 = (MODE == 1) ? g_nsrc[r0] : 1.f;
        float ns1 = (MODE == 1) ? g_nsrc[r0 + 8] : 1.f;
#pragma unroll
        for (int j = 0; j < 4; j++) {
            int col = n0 + j * 8 + tig * 2;
            float bx = bias[col], by = bias[col + 1];
            float2 v0, v1;
            v0.x = fmaxf(D[i][j][0] + bx, 0.f) * ns0;
            v0.y = fmaxf(D[i][j][1] + by, 0.f) * ns0;
            v1.x = fmaxf(D[i][j][2] + bx, 0.f) * ns1;
            v1.y = fmaxf(D[i][j][3] + by, 0.f) * ns1;
            *(float2*)&out[(size_t)r0 * 128 + col] = v0;
            *(float2*)&out[(size_t)(r0 + 8) * 128 + col] = v1;
        }
    }
}

// ================= init kernel: hA = (x @ W_init) * nsrc =================
__global__ void __launch_bounds__(512, 1)
k_init_mma(const float* __restrict__ x) {
    extern __shared__ float sm[];
    float* As = sm;                    // [128][LDI]
    float* Bs = sm + 128 * LDI;        // [128][LDI]
    const int tid = threadIdx.x;
    const int lane = tid & 31, warp = tid >> 5;
    const int rowBase = blockIdx.x * 128;

    // B from g_WTi (float4: 128 rows x 20 quads)
    {
        const float4* Wt4 = (const float4*)g_WTi;
        for (int idx = tid; idx < 128 * (KP_I / 4); idx += 512) {
            int n = idx / (KP_I / 4), kq = idx - n * (KP_I / 4);
            *(float4*)&Bs[n * LDI + kq * 4] = Wt4[idx];
        }
    }
    // A: [128 r][80 k], zero-pad k>=74
    for (int idx = tid; idx < 128 * KP_I; idx += 512) {
        int r = idx / KP_I, k = idx - r * KP_I;
        float v = (k < INF) ? to_tf32(x[(size_t)(rowBase + r) * INF + k]) : 0.f;
        As[r * LDI + k] = v;
    }
    __syncthreads();

    const int wr = warp >> 2, wc = warp & 3;
    const int m0 = wr * 32, n0 = wc * 32;
    const int g = lane >> 2, tig = lane & 3;

    float D[2][4][4];
#pragma unroll
    for (int i = 0; i < 2; i++)
#pragma unroll
        for (int j = 0; j < 4; j++)
#pragma unroll
            for (int q = 0; q < 4; q++) D[i][j][q] = 0.f;

    const uint32_t* Au = (const uint32_t*)As;
    const uint32_t* Bu = (const uint32_t*)Bs;

#pragma unroll
    for (int k0 = 0; k0 < KP_I; k0 += 8) {
        uint32_t a[2][4];
#pragma unroll
        for (int i = 0; i < 2; i++) {
            int mr = m0 + i * 16 + g;
            a[i][0] = Au[mr * LDI + k0 + tig];
            a[i][1] = Au[(mr + 8) * LDI + k0 + tig];
            a[i][2] = Au[mr * LDI + k0 + tig + 4];
            a[i][3] = Au[(mr + 8) * LDI + k0 + tig + 4];
        }
        uint32_t b[4][2];
#pragma unroll
        for (int j = 0; j < 4; j++) {
            int nc = n0 + j * 8 + g;
            b[j][0] = Bu[nc * LDI + k0 + tig];
            b[j][1] = Bu[nc * LDI + k0 + tig + 4];
        }
#pragma unroll
        for (int i = 0; i < 2; i++)
#pragma unroll
            for (int j = 0; j < 4; j++)
                mma_tf32(D[i][j], a[i][0], a[i][1], a[i][2], a[i][3], b[j][0], b[j][1]);
    }

#pragma unroll
    for (int i = 0; i < 2; i++) {
        int r0 = rowBase + m0 + i * 16 + g;
        float ns0 = g_nsrc[r0];
        float ns1 = g_nsrc[r0 + 8];
#pragma unroll
        for (int j = 0; j < 4; j++) {
            int col = n0 + j * 8 + tig * 2;
            float2 v0, v1;
            v0.x = D[i][j][0] * ns0;
            v0.y = D[i][j][1] * ns0;
            v1.x = D[i][j][2] * ns1;
            v1.y = D[i][j][3] * ns1;
            *(float2*)&g_hA[(size_t)r0 * 128 + col] = v0;
            *(float2*)&g_hA[(size_t)(r0 + 8) * 128 + col] = v1;
        }
    }
}

// ---------------- launch ----------------
extern "C" void kernel_launch(void* const* d_in, const int* in_sizes, int n_in,
                              void* d_out, int out_size) {
    (void)in_sizes; (void)n_in; (void)out_size;
    const float* x   = (const float*)d_in[0];
    const int*   src = (const int*)d_in[1];
    const int*   dst = (const int*)d_in[2];
    const float* Wi  = (const float*)d_in[3];
    const float* W1  = (const float*)d_in[4];
    const float* b1  = (const float*)d_in[5];
    const float* W2  = (const float*)d_in[6];
    const float* b2  = (const float*)d_in[7];
    const float* W3  = (const float*)d_in[8];
    const float* b3  = (const float*)d_in[9];
    float* out = (float*)d_out;

    const int SMEM_LAYER = (128 * LDA + 128 * LDA) * 4;  // 135,168 B (1 CTA/SM)
    const int SMEM_INIT  = (128 * LDI + 128 * LDI) * 4;  //  86,016 B

    cudaFuncSetAttribute(k_init_mma, cudaFuncAttributeMaxDynamicSharedMemorySize, SMEM_INIT);
    cudaFuncSetAttribute(k_layer_mma<1>, cudaFuncAttributeMaxDynamicSharedMemorySize, SMEM_LAYER);
    cudaFuncSetAttribute(k_layer_mma<2>, cudaFuncAttributeMaxDynamicSharedMemorySize, SMEM_LAYER);

    float *hA, *hB, *wt1, *wt2, *wt3;
    cudaGetSymbolAddress((void**)&hA, g_hA);
    cudaGetSymbolAddress((void**)&hB, g_hB);
    cudaGetSymbolAddress((void**)&wt1, g_WT1);
    cudaGetSymbolAddress((void**)&wt2, g_WT2);
    cudaGetSymbolAddress((void**)&wt3, g_WT3);

    // graph preprocessing
    k_zero<<<(NN + 255) / 256, 256>>>();
    k_count<<<1024, 256>>>(src, dst);
    k_scanA<<<NN / 1024, 1024>>>();
    k_scanB<<<1, 128>>>();
    k_scanC_norm<<<(NN + 255) / 256, 256>>>();
    k_fill<<<1024, 256>>>(src, dst);
    k_wt<<<64, 256>>>(Wi, W1, W2, W3);

    // hA = (x @ W_init) * nrm_src
    k_init_mma<<<NN / 128, 512, SMEM_INIT>>>(x);

    // 3 GCN layers (ping-pong; layer 3 writes d_out unscaled)
    k_layer_mma<1><<<NN / 128, 512, SMEM_LAYER>>>(hA, wt1, b1, hB);
    k_layer_mma<1><<<NN / 128, 512, SMEM_LAYER>>>(hB, wt2, b2, hA);
    k_layer_mma<2><<<NN / 128, 512, SMEM_LAYER>>>(hA, wt3, b3, out);
}